// round 1
// baseline (speedup 1.0000x reference)
#include <cuda_runtime.h>

#define BB   32
#define NN   1024
#define WW_  128
#define RR   4
#define SEQ  512
#define DIN  512
#define IFACE 919

// Flattened output offsets (tuple concat order: out, memory, link, usage, prec, ww, rw)
#define OUT_OFF    0ull
#define MEM_OFF    16384ull
#define LINK_OFF   4210688ull
#define USAGE_OFF  37765120ull
#define PREC_OFF   37797888ull
#define WWO_OFF    37830656ull
#define RW_OFF     37863424ull
#define LINK_ELEMS 33554432ull

// Scratch (no allocations allowed)
__device__ float g_part[8 * BB * DIN];
__device__ float g_meanx[BB * DIN];
__device__ float g_iface[BB * IFACE];
__device__ float g_er[BB * WW_];
__device__ float g_wv[BB * WW_];
__device__ float g_q[BB * RR];   // rw value per (b,r): read_modes[b,1,r]/1024
__device__ float g_u[BB];        // usage value per batch

__device__ __forceinline__ float sigmoidf(float x) {
    return 1.0f / (1.0f + expf(-x));
}

// ---------------------------------------------------------------------------
// Kernel 1a: partial mean of x over seq. grid (B, 8), block 128 (float4 over d)
// ---------------------------------------------------------------------------
__global__ void k_mean_part(const float* __restrict__ x) {
    int b = blockIdx.x, c = blockIdx.y, t = threadIdx.x;
    const float4* xp = (const float4*)(x + (size_t)b * SEQ * DIN);
    float4 acc = make_float4(0.f, 0.f, 0.f, 0.f);
    int s0 = c * 64;
#pragma unroll 4
    for (int s = s0; s < s0 + 64; s++) {
        float4 v = xp[s * 128 + t];
        acc.x += v.x; acc.y += v.y; acc.z += v.z; acc.w += v.w;
    }
    ((float4*)g_part)[(c * BB + b) * 128 + t] = acc;
}

// Kernel 1b: combine partials -> mean_x. grid B, block 512
__global__ void k_mean_comb() {
    int b = blockIdx.x, t = threadIdx.x;
    float s = 0.f;
#pragma unroll
    for (int c = 0; c < 8; c++) s += g_part[(c * BB + b) * DIN + t];
    g_meanx[b * DIN + t] = s * (1.0f / 512.0f);
}

// ---------------------------------------------------------------------------
// Kernel 2: iface = mean_x @ W  (32x512 @ 512x919). grid (B, 8), block 128
// ---------------------------------------------------------------------------
__global__ void k_iface(const float* __restrict__ Wm) {
    int b = blockIdx.x;
    int j = blockIdx.y * 128 + threadIdx.x;
    __shared__ float mx[DIN];
    for (int i = threadIdx.x; i < DIN; i += 128) mx[i] = g_meanx[b * DIN + i];
    __syncthreads();
    if (j >= IFACE) return;
    float acc = 0.f;
#pragma unroll 8
    for (int k = 0; k < DIN; k++) acc = fmaf(mx[k], Wm[k * IFACE + j], acc);
    g_iface[b * IFACE + j] = acc;
}

// ---------------------------------------------------------------------------
// Kernel 3: per-batch activations + serial ww/prec + "out" section.
// grid B, block 128
// ---------------------------------------------------------------------------
__global__ void k_prep(float* __restrict__ out) {
    int b = blockIdx.x, t = threadIdx.x;
    const float* f = g_iface + b * IFACE;
    __shared__ float s_rm1[RR], s_fg[RR], s_q[RR];

    // erase_vector = sigmoid(iface[645:773]); write_vector = iface[773:901]
    g_er[b * WW_ + t] = sigmoidf(f[645 + t]);
    g_wv[b * WW_ + t] = f[773 + t];

    if (t < RR) {
        // read_modes softmax over 3 modes; only mode 1 (lookup) survives
        float m0 = f[907 + t], m1 = f[911 + t], m2 = f[915 + t];
        float mx = fmaxf(m0, fmaxf(m1, m2));
        float e0 = expf(m0 - mx), e1 = expf(m1 - mx), e2 = expf(m2 - mx);
        float rm1 = e1 / (e0 + e1 + e2);
        s_rm1[t] = rm1;
        float q = rm1 * (1.0f / 1024.0f);   // rw value (exact: /2^10)
        s_q[t] = q;
        g_q[b * RR + t] = q;
        s_fg[t] = sigmoidf(f[901 + t]);     // free gates
    }
    __syncthreads();

    // out[b, w*4+r] = 1e-6 * rm1[r]  (read_vectors independent of w)
    float4 ov = make_float4(1e-6f * s_rm1[0], 1e-6f * s_rm1[1],
                            1e-6f * s_rm1[2], 1e-6f * s_rm1[3]);
    ((float4*)(out + OUT_OFF))[b * 128 + t] = ov;

    if (t == 0) {
        float ret = 1.0f;
#pragma unroll
        for (int r = 0; r < RR; r++) ret *= (1.0f - s_fg[r] * s_q[r]);
        float u = 1e-6f * ret;              // usage (constant over n)
        g_u[b] = u;

        float ag = sigmoidf(f[905]);
        float wg = sigmoidf(f[906]);
        float base = (1.0f - ag) * (1.0f / 1024.0f);  // (1-ag)*lookup_w
        float one_m_u = 1.0f - u;
        float shifted = 1.0f;               // shifted[i] = u^i (seq cumprod)
        for (int n = 0; n < NN; n++) {
            float alloc = one_m_u * shifted;
            float ww = wg * (ag * alloc + base);
            out[WWO_OFF + (size_t)b * NN + n]  = ww;
            out[PREC_OFF + (size_t)b * NN + n] = ww;  // prec == ww
            shifted *= u;                   // underflows to 0 by n~8
        }
    }
}

// ---------------------------------------------------------------------------
// Kernel 4: big fills: memory (float4), rw (float4), usage. block 256
// memory: 1,048,576 f4 -> 4096 blocks; rw: 32768 f4 -> 128; usage: 32768 -> 128
// ---------------------------------------------------------------------------
__global__ void k_fill(float* __restrict__ out) {
    int bid = blockIdx.x, t = threadIdx.x;
    if (bid < 4096) {
        int v = bid * 256 + t;         // float4 index into memory
        int b = v >> 15;               // 32768 f4 per batch
        int rem = v & 32767;
        int n = rem >> 5;
        int w4 = rem & 31;
        float ww = __ldg(out + WWO_OFF + (size_t)b * NN + n);
        float4 e  = ((const float4*)g_er)[b * 32 + w4];
        float4 wv = ((const float4*)g_wv)[b * 32 + w4];
        float4 m;
        m.x = 1e-6f * (1.0f - ww * e.x) + ww * wv.x;
        m.y = 1e-6f * (1.0f - ww * e.y) + ww * wv.y;
        m.z = 1e-6f * (1.0f - ww * e.z) + ww * wv.z;
        m.w = 1e-6f * (1.0f - ww * e.w) + ww * wv.w;
        ((float4*)(out + MEM_OFF))[v] = m;
    } else if (bid < 4224) {
        int i = (bid - 4096) * 256 + t;  // (b,n) index
        int b = i >> 10;
        ((float4*)(out + RW_OFF))[i] = ((const float4*)g_q)[b];
    } else {
        int i = (bid - 4224) * 256 + t;
        out[USAGE_OFF + i] = g_u[i >> 10];
    }
}

extern "C" void kernel_launch(void* const* d_in, const int* in_sizes, int n_in,
                              void* d_out, int out_size) {
    const float* x  = (const float*)d_in[0];
    const float* Wm = (const float*)d_in[1];
    float* out = (float*)d_out;

    // link output is identically zero (prec0 == 0, link0 == 0)
    cudaMemsetAsync(out + LINK_OFF, 0, LINK_ELEMS * sizeof(float));

    k_mean_part<<<dim3(BB, 8), 128>>>(x);
    k_mean_comb<<<BB, 512>>>();
    k_iface<<<dim3(BB, 8), 128>>>(Wm);
    k_prep<<<BB, 128>>>(out);
    k_fill<<<4352, 256>>>(out);
}

// round 2
// speedup vs baseline: 1.1547x; 1.1547x over previous
#include <cuda_runtime.h>

#define BB   32
#define NN   1024
#define WW_  128
#define RR   4
#define SEQ  512
#define DIN  512
#define IFACE 919

// Flattened output offsets (tuple concat order: out, memory, link, usage, prec, ww, rw)
#define OUT_OFF    0ull
#define MEM_OFF    16384ull
#define LINK_OFF   4210688ull
#define USAGE_OFF  37765120ull
#define PREC_OFF   37797888ull
#define WWO_OFF    37830656ull
#define RW_OFF     37863424ull
#define LINK_F4    8388608ull      // 33,554,432 floats / 4

// Scratch (no allocations allowed)
__device__ float g_part[16 * BB * DIN];
__device__ float g_iface[BB * IFACE];
__device__ float g_er[BB * WW_];
__device__ float g_wv[BB * WW_];
__device__ float g_q[BB * RR];   // rw value per (b,r): read_modes[b,1,r]/1024
__device__ float g_u[BB];        // usage value per batch

__device__ __forceinline__ float sigmoidf(float x) {
    return 1.0f / (1.0f + expf(-x));
}

// ---------------------------------------------------------------------------
// K1: fused link-zero (134MB) + partial mean of x (33.5MB read).
// grid 4096 blocks x 256 threads. Blocks 0..255: mean partials (b,c).
// Blocks 256..4095: grid-stride float4 zero of link region.
// ---------------------------------------------------------------------------
__global__ void k1_zero_mean(const float* __restrict__ x, float* __restrict__ out) {
    int bid = blockIdx.x, t = threadIdx.x;
    if (bid < 256) {
        int b = bid >> 3, c = bid & 7;
        int col = t & 127;           // float4 column within 512 floats
        int h   = t >> 7;            // seq-half within the 64-row chunk
        const float4* xp = (const float4*)(x + (size_t)b * SEQ * DIN);
        float4 acc = make_float4(0.f, 0.f, 0.f, 0.f);
        int s0 = c * 64 + h * 32;
#pragma unroll 4
        for (int s = s0; s < s0 + 32; s++) {
            float4 v = xp[s * 128 + col];
            acc.x += v.x; acc.y += v.y; acc.z += v.z; acc.w += v.w;
        }
        ((float4*)g_part)[((c * 2 + h) * BB + b) * 128 + col] = acc;
    } else {
        float4 z = make_float4(0.f, 0.f, 0.f, 0.f);
        float4* p = (float4*)(out + LINK_OFF);
        size_t stride = (size_t)(gridDim.x - 256) * 256;
        for (size_t i = (size_t)(bid - 256) * 256 + t; i < LINK_F4; i += stride)
            p[i] = z;
    }
}

// ---------------------------------------------------------------------------
// K2: combine partials -> mean in smem, then iface = mean_x @ W.
// grid (32, 8), block 128
// ---------------------------------------------------------------------------
__global__ void k2_iface(const float* __restrict__ Wm) {
    int b = blockIdx.x;
    int j = blockIdx.y * 128 + threadIdx.x;
    __shared__ float mx[DIN];
    for (int i = threadIdx.x; i < DIN; i += 128) {
        float s = 0.f;
#pragma unroll
        for (int c = 0; c < 16; c++) s += g_part[(c * BB + b) * DIN + i];
        mx[i] = s * (1.0f / 512.0f);
    }
    __syncthreads();
    if (j >= IFACE) return;
    float acc = 0.f;
#pragma unroll 8
    for (int k = 0; k < DIN; k++) acc = fmaf(mx[k], Wm[k * IFACE + j], acc);
    g_iface[b * IFACE + j] = acc;
}

// ---------------------------------------------------------------------------
// K3: per-batch activations + parallel ww/prec + "out" section. grid B, block 128.
// cumprod of usage u underflows to exactly 0 by n=8 (u ~ 1e-6), so thread 0
// builds a 16-entry exact power table; all threads fan out the 1024 stores.
// ---------------------------------------------------------------------------
__global__ void k3_prep(float* __restrict__ out) {
    int b = blockIdx.x, t = threadIdx.x;
    const float* f = g_iface + b * IFACE;
    __shared__ float s_rm1[RR], s_fg[RR], s_q[RR];
    __shared__ float s_pw[16];
    __shared__ float s_c1, s_c2;

    // erase_vector = sigmoid(iface[645:773]); write_vector = iface[773:901]
    g_er[b * WW_ + t] = sigmoidf(f[645 + t]);
    g_wv[b * WW_ + t] = f[773 + t];

    if (t < RR) {
        // read_modes softmax over 3 modes; only mode 1 (lookup) contributes
        float m0 = f[907 + t], m1 = f[911 + t], m2 = f[915 + t];
        float mx = fmaxf(m0, fmaxf(m1, m2));
        float e0 = expf(m0 - mx), e1 = expf(m1 - mx), e2 = expf(m2 - mx);
        float rm1 = e1 / (e0 + e1 + e2);
        s_rm1[t] = rm1;
        float q = rm1 * (1.0f / 1024.0f);   // exact /2^10
        s_q[t] = q;
        g_q[b * RR + t] = q;
        s_fg[t] = sigmoidf(f[901 + t]);     // free gates
    }
    __syncthreads();

    // out[b, w*4+r] = 1e-6 * rm1[r]  (read_vectors independent of w)
    float4 ov = make_float4(1e-6f * s_rm1[0], 1e-6f * s_rm1[1],
                            1e-6f * s_rm1[2], 1e-6f * s_rm1[3]);
    ((float4*)(out + OUT_OFF))[b * 128 + t] = ov;

    if (t == 0) {
        float ret = 1.0f;
#pragma unroll
        for (int r = 0; r < RR; r++) ret *= (1.0f - s_fg[r] * s_q[r]);
        float u = 1e-6f * ret;              // usage (constant over n)
        g_u[b] = u;

        float ag = sigmoidf(f[905]);
        float wg = sigmoidf(f[906]);
        s_c1 = wg * ag * (1.0f - u);
        s_c2 = wg * (1.0f - ag) * (1.0f / 1024.0f);

        float sh = 1.0f;                    // exact sequential cumprod prefix
#pragma unroll
        for (int i = 0; i < 16; i++) { s_pw[i] = sh; sh *= u; }
    }
    __syncthreads();

    float c1 = s_c1, c2 = s_c2;
#pragma unroll
    for (int n = t; n < NN; n += 128) {
        float shifted = (n < 16) ? s_pw[n] : 0.0f;
        float ww = fmaf(c1, shifted, c2);
        out[WWO_OFF + (size_t)b * NN + n]  = ww;
        out[PREC_OFF + (size_t)b * NN + n] = ww;  // prec == ww
    }
}

// ---------------------------------------------------------------------------
// K4: big fills: memory (float4), rw (float4), usage. block 256
// ---------------------------------------------------------------------------
__global__ void k4_fill(float* __restrict__ out) {
    int bid = blockIdx.x, t = threadIdx.x;
    if (bid < 4096) {
        int v = bid * 256 + t;         // float4 index into memory
        int b = v >> 15;               // 32768 f4 per batch
        int rem = v & 32767;
        int n = rem >> 5;
        int w4 = rem & 31;
        float ww = __ldg(out + WWO_OFF + (size_t)b * NN + n);
        float4 e  = ((const float4*)g_er)[b * 32 + w4];
        float4 wv = ((const float4*)g_wv)[b * 32 + w4];
        float4 m;
        m.x = 1e-6f * (1.0f - ww * e.x) + ww * wv.x;
        m.y = 1e-6f * (1.0f - ww * e.y) + ww * wv.y;
        m.z = 1e-6f * (1.0f - ww * e.z) + ww * wv.z;
        m.w = 1e-6f * (1.0f - ww * e.w) + ww * wv.w;
        ((float4*)(out + MEM_OFF))[v] = m;
    } else if (bid < 4224) {
        int i = (bid - 4096) * 256 + t;  // (b,n) index
        int b = i >> 10;
        ((float4*)(out + RW_OFF))[i] = ((const float4*)g_q)[b];
    } else {
        int i = (bid - 4224) * 256 + t;
        out[USAGE_OFF + i] = g_u[i >> 10];
    }
}

extern "C" void kernel_launch(void* const* d_in, const int* in_sizes, int n_in,
                              void* d_out, int out_size) {
    const float* x  = (const float*)d_in[0];
    const float* Wm = (const float*)d_in[1];
    float* out = (float*)d_out;

    k1_zero_mean<<<4096, 256>>>(x, out);
    k2_iface<<<dim3(BB, 8), 128>>>(Wm);
    k3_prep<<<BB, 128>>>(out);
    k4_fill<<<4352, 256>>>(out);
}